// round 2
// baseline (speedup 1.0000x reference)
#include <cuda_runtime.h>
#include <cuda_bf16.h>
#include <cstdint>

// Problem constants
#define BB   8
#define CC   256
#define HH   128
#define WW   128
#define GG   8       // ska groups (32 ch each)
#define NPIX 16384   // H*W
#define EPSV 1e-5f

// Scratch (device globals; allocation-free rule)
__device__ float g_ska[BB * CC * NPIX];   // SKA output (residual + conv input)
__device__ float g_t[BB * CC * NPIX];     // after conv3x3+BN+ReLU
__device__ float g_w2t[CC * CC];          // transposed w2 with s2 folded
__device__ float g_s1[CC], g_bb1[CC], g_s2[CC], g_bb2[CC];

// ---------- packed f32x2 helpers ----------
__device__ __forceinline__ unsigned long long pack2(float a, float b) {
    unsigned long long r;
    asm("mov.b64 %0, {%1, %2};" : "=l"(r) : "f"(a), "f"(b));
    return r;
}
__device__ __forceinline__ unsigned long long fma2(unsigned long long a,
                                                   unsigned long long b,
                                                   unsigned long long c) {
    unsigned long long d;
    asm("fma.rn.f32x2 %0, %1, %2, %3;" : "=l"(d) : "l"(a), "l"(b), "l"(c));
    return d;
}
__device__ __forceinline__ float2 unpack2(unsigned long long v) {
    float2 f;
    asm("mov.b64 {%0, %1}, %2;" : "=f"(f.x), "=f"(f.y) : "l"(v));
    return f;
}

// ---------- prep: fold BN params ----------
__global__ void prep_bn(const float* __restrict__ g1, const float* __restrict__ b1,
                        const float* __restrict__ m1, const float* __restrict__ v1,
                        const float* __restrict__ g2, const float* __restrict__ b2,
                        const float* __restrict__ m2, const float* __restrict__ v2) {
    int c = threadIdx.x;
    if (c < CC) {
        float i1 = g1[c] * rsqrtf(v1[c] + EPSV);
        g_s1[c]  = i1;
        g_bb1[c] = b1[c] - m1[c] * i1;
        float i2 = g2[c] * rsqrtf(v2[c] + EPSV);
        g_s2[c]  = i2;
        g_bb2[c] = b2[c] - m2[c] * i2;
    }
}

// ---------- prep: transpose w2 with s2 fold ----------
__global__ void prep_w2t(const float* __restrict__ w2) {
    int i  = blockIdx.x * 256 + threadIdx.x;  // 65536 total
    int co = i >> 8;
    int ci = i & 255;
    g_w2t[ci * 256 + co] = w2[i] * g_s2[co];
}

// ---------- SKA: spatially-varying 3x3 aggregation ----------
// grid (H/2, B*G), block 256: 2 output rows per block (x row reuse 2x vs 3x).
__global__ void ska_kernel(const float* __restrict__ x, const float* __restrict__ dw) {
    int h0 = blockIdx.x * 2;
    int bg = blockIdx.y;                 // b*G + g
    int b  = bg >> 3, g = bg & 7;
    int tid = threadIdx.x;
    int hr = tid >> 7;                   // 0/1: which output row
    int w  = tid & 127;

    __shared__ float rows[4][130];
    if (tid < 4) {                       // zero halo columns (never overwritten)
        rows[tid][0]   = 0.f;
        rows[tid][129] = 0.f;
    }

    int h = h0 + hr;
    float dwv[9];
    const float* dp = dw + (size_t)bg * 9 * NPIX + h * WW + w;
#pragma unroll
    for (int k = 0; k < 9; ++k) dwv[k] = dp[k * NPIX];

    const float* xb = x + (size_t)(b * CC + g * 32) * NPIX;
    float* ob = g_ska + (size_t)(b * CC + g * 32) * NPIX + h * WW + w;

    for (int c = 0; c < 32; ++c) {
        __syncthreads();
        const float* xc = xb + c * NPIX;
#pragma unroll
        for (int j2 = 0; j2 < 2; ++j2) {
            int j  = hr * 2 + j2;        // 0..3
            int hh = h0 - 1 + j;
            rows[j][w + 1] = ((unsigned)hh < (unsigned)HH) ? xc[hh * WW + w] : 0.f;
        }
        __syncthreads();
        float acc = 0.f;
#pragma unroll
        for (int r = 0; r < 3; ++r)
#pragma unroll
            for (int kw = 0; kw < 3; ++kw)
                acc = fmaf(rows[hr + r][w + kw], dwv[r * 3 + kw], acc);
        ob[c * NPIX] = acc;
    }
}

// ---------- grouped 3x3 conv + BN + ReLU (f32x2) ----------
// grid (8,8,B*8): 16x16 pixel tile, one conv-group (32 in -> 32 out).
// 256 threads: tid>>6 -> 8-cout slab (4 pairs), tid&63 -> 2x2 pixel quad.
// Per cin: 36 weight LDS.64 feed 144 fma2 (1:4).
__global__ void __launch_bounds__(256, 2)
conv3_kernel(const float* __restrict__ roi, const float* __restrict__ w1) {
    int bz  = blockIdx.z;
    int b   = bz >> 3, vg = bz & 7;
    int px0 = blockIdx.x * 16, py0 = blockIdx.y * 16;
    int tid = threadIdx.x;

    __shared__ float ws2[32 * 9 * 34];   // [cin][tap][co padded to 34]
    __shared__ float xt[18][20];

    // stage weights (coalesced read), fold s1, transposed write
    {
        const float* slab = w1 + vg * 32 * 288;  // w1[(vg*32+co)*288 + k]
        for (int j = tid; j < 9216; j += 256) {
            int co = j / 288;
            int k  = j - co * 288;               // cin*9 + tap
            ws2[k * 34 + co] = slab[j] * g_s1[vg * 32 + co];
        }
    }

    int cog = tid >> 6;          // 0..3 -> cout base cog*8
    int qid = tid & 63;
    int py  = (qid >> 3) * 2;    // 0..14 even
    int px  = (qid & 7) * 2;     // 0..14 even

    unsigned long long acc[4][4]; // [co pair][quad pixel], lanes = {co, co+1}
#pragma unroll
    for (int i = 0; i < 4; ++i)
#pragma unroll
        for (int j = 0; j < 4; ++j) acc[i][j] = 0ull;

    const float* rp = roi + b * NPIX;

    for (int cin = 0; cin < 32; ++cin) {
        __syncthreads();
        const float* sp = g_ska + (size_t)(b * CC + vg * 32 + cin) * NPIX;
        for (int i = tid; i < 324; i += 256) {
            int r  = i / 18, cc2 = i - r * 18;
            int hh = py0 + r - 1, ww2 = px0 + cc2 - 1;
            float v = 0.f;
            if ((unsigned)hh < (unsigned)HH && (unsigned)ww2 < (unsigned)WW) {
                int off = hh * WW + ww2;
                v = sp[off] * rp[off];
            }
            xt[r][cc2] = v;
        }
        __syncthreads();

        // prepack 4x4 window once
        unsigned long long xp[16];
#pragma unroll
        for (int r = 0; r < 4; ++r)
#pragma unroll
            for (int c = 0; c < 4; ++c) {
                float v = xt[py + r][px + c];
                xp[r * 4 + c] = pack2(v, v);
            }

        const float* wb = ws2 + cin * 9 * 34 + cog * 8;
#pragma unroll
        for (int tap = 0; tap < 9; ++tap) {
            int r = tap / 3, kw = tap - r * 3;
            unsigned long long wv[4];
#pragma unroll
            for (int c2 = 0; c2 < 4; ++c2)
                wv[c2] = *(const unsigned long long*)(wb + tap * 34 + c2 * 2);
#pragma unroll
            for (int c2 = 0; c2 < 4; ++c2) {
                acc[c2][0] = fma2(wv[c2], xp[r * 4 + kw],           acc[c2][0]);
                acc[c2][1] = fma2(wv[c2], xp[r * 4 + kw + 1],       acc[c2][1]);
                acc[c2][2] = fma2(wv[c2], xp[(r + 1) * 4 + kw],     acc[c2][2]);
                acc[c2][3] = fma2(wv[c2], xp[(r + 1) * 4 + kw + 1], acc[c2][3]);
            }
        }
    }

    int hy = py0 + py, wx = px0 + px;
#pragma unroll
    for (int c2 = 0; c2 < 4; ++c2) {
        int cg = vg * 32 + cog * 8 + c2 * 2;
        float bbA = g_bb1[cg], bbB = g_bb1[cg + 1];
#pragma unroll
        for (int i = 0; i < 2; ++i) {
            float2 eA = unpack2(acc[c2][i * 2 + 0]);  // pixel (hy+i, wx)
            float2 eB = unpack2(acc[c2][i * 2 + 1]);  // pixel (hy+i, wx+1)
            float2 rowA = make_float2(fmaxf(eA.x + bbA, 0.f), fmaxf(eB.x + bbA, 0.f));
            float2 rowB = make_float2(fmaxf(eA.y + bbB, 0.f), fmaxf(eB.y + bbB, 0.f));
            size_t oa = (size_t)(b * CC + cg) * NPIX + (hy + i) * WW + wx;
            *(float2*)(g_t + oa)        = rowA;
            *(float2*)(g_t + oa + NPIX) = rowB;
        }
    }
}

// ---------- 1x1 conv (GEMM) + BN + residual (f32x2) ----------
// grid (128, 2, B): 128 px x 128 co tile. 256 threads: 8 co x 8 px per thread.
// Per k-step: 6 LDS feed 32 fma2.
__global__ void __launch_bounds__(256, 2)
conv1x1_kernel(float* __restrict__ out) {
    int p0  = blockIdx.x * 128;
    int co0 = blockIdx.y * 128;
    int b   = blockIdx.z;
    int tid = threadIdx.x;
    int tx  = tid & 15;   // px direction (8 px each)
    int ty  = tid >> 4;   // co direction (8 co each)

    __shared__ float As[16][128];  // w2t[k][co]  (s2 folded)
    __shared__ float Bs[16][128];  // t[k][p]

    unsigned long long acc[4][8];  // [co pair][px], lanes = {co, co+1}
#pragma unroll
    for (int i = 0; i < 4; ++i)
#pragma unroll
        for (int j = 0; j < 8; ++j) acc[i][j] = 0ull;

    const float* tb = g_t + (size_t)b * CC * NPIX;

    for (int kb = 0; kb < 16; ++kb) {
        __syncthreads();
        for (int i = tid; i < 2048; i += 256) {
            int kk = i >> 7, c = i & 127;
            As[kk][c] = g_w2t[(kb * 16 + kk) * 256 + co0 + c];
            Bs[kk][c] = tb[(size_t)(kb * 16 + kk) * NPIX + p0 + c];
        }
        __syncthreads();
#pragma unroll
        for (int kk = 0; kk < 16; ++kk) {
            const float4* bp4 = (const float4*)&Bs[kk][tx * 8];
            float4 b0 = bp4[0], b1 = bp4[1];
            unsigned long long bp[8];
            bp[0] = pack2(b0.x, b0.x); bp[1] = pack2(b0.y, b0.y);
            bp[2] = pack2(b0.z, b0.z); bp[3] = pack2(b0.w, b0.w);
            bp[4] = pack2(b1.x, b1.x); bp[5] = pack2(b1.y, b1.y);
            bp[6] = pack2(b1.z, b1.z); bp[7] = pack2(b1.w, b1.w);
            const float* ar = &As[kk][ty * 8];
#pragma unroll
            for (int c2 = 0; c2 < 4; ++c2) {
                unsigned long long wv = *(const unsigned long long*)(ar + c2 * 2);
#pragma unroll
                for (int j = 0; j < 8; ++j)
                    acc[c2][j] = fma2(wv, bp[j], acc[c2][j]);
            }
        }
    }

    // epilogue: out = ska + dot + bb2
#pragma unroll
    for (int c2 = 0; c2 < 4; ++c2) {
        int co = co0 + ty * 8 + c2 * 2;
        float bbA = g_bb2[co], bbB = g_bb2[co + 1];
        float2 f[8];
#pragma unroll
        for (int j = 0; j < 8; ++j) f[j] = unpack2(acc[c2][j]);
        size_t i0 = (size_t)(b * CC + co) * NPIX + p0 + tx * 8;
        float4 sA0 = *(const float4*)(g_ska + i0);
        float4 sA1 = *(const float4*)(g_ska + i0 + 4);
        float4 sB0 = *(const float4*)(g_ska + i0 + NPIX);
        float4 sB1 = *(const float4*)(g_ska + i0 + NPIX + 4);
        float4 oA0 = make_float4(sA0.x + f[0].x + bbA, sA0.y + f[1].x + bbA,
                                 sA0.z + f[2].x + bbA, sA0.w + f[3].x + bbA);
        float4 oA1 = make_float4(sA1.x + f[4].x + bbA, sA1.y + f[5].x + bbA,
                                 sA1.z + f[6].x + bbA, sA1.w + f[7].x + bbA);
        float4 oB0 = make_float4(sB0.x + f[0].y + bbB, sB0.y + f[1].y + bbB,
                                 sB0.z + f[2].y + bbB, sB0.w + f[3].y + bbB);
        float4 oB1 = make_float4(sB1.x + f[4].y + bbB, sB1.y + f[5].y + bbB,
                                 sB1.z + f[6].y + bbB, sB1.w + f[7].y + bbB);
        *(float4*)(out + i0)            = oA0;
        *(float4*)(out + i0 + 4)        = oA1;
        *(float4*)(out + i0 + NPIX)     = oB0;
        *(float4*)(out + i0 + NPIX + 4) = oB1;
    }
}

extern "C" void kernel_launch(void* const* d_in, const int* in_sizes, int n_in,
                              void* d_out, int out_size) {
    const float* x   = (const float*)d_in[0];
    const float* dw  = (const float*)d_in[1];
    const float* roi = (const float*)d_in[2];
    const float* w1  = (const float*)d_in[3];
    const float* g1  = (const float*)d_in[4];
    const float* b1  = (const float*)d_in[5];
    const float* m1  = (const float*)d_in[6];
    const float* v1  = (const float*)d_in[7];
    const float* w2  = (const float*)d_in[8];
    const float* g2  = (const float*)d_in[9];
    const float* b2  = (const float*)d_in[10];
    const float* m2  = (const float*)d_in[11];
    const float* v2  = (const float*)d_in[12];
    float* out = (float*)d_out;

    prep_bn<<<1, 256>>>(g1, b1, m1, v1, g2, b2, m2, v2);
    prep_w2t<<<256, 256>>>(w2);
    ska_kernel<<<dim3(HH / 2, BB * GG), 256>>>(x, dw);
    conv3_kernel<<<dim3(8, 8, BB * 8), 256>>>(roi, w1);
    conv1x1_kernel<<<dim3(128, 2, BB), 256>>>(out);
}

// round 3
// speedup vs baseline: 1.3397x; 1.3397x over previous
#include <cuda_runtime.h>
#include <cuda_bf16.h>
#include <cstdint>

// Problem constants
#define BB   8
#define CC   256
#define HH   128
#define WW   128
#define GG   8       // ska groups (32 ch each)
#define NPIX 16384   // H*W
#define EPSV 1e-5f
#define H2   130     // padded rows
#define W2   132     // padded cols (16B-friendly)

// Scratch (device globals; allocation-free rule). Zero-initialized at load:
// g_skar's 1-pixel border is never written -> stays zero (implicit padding).
__device__ float g_ska[BB * CC * NPIX];       // raw SKA output (residual)
__device__ float g_skar[BB * CC * H2 * W2];   // ska*roi, zero-padded (conv3 input)
__device__ float g_t[BB * CC * NPIX];         // after conv3x3+BN+ReLU
__device__ float g_w2t[CC * CC];              // transposed w2 with s2 folded
__device__ float g_s1[CC], g_bb1[CC], g_s2[CC], g_bb2[CC];

// ---------- packed f32x2 helpers ----------
__device__ __forceinline__ unsigned long long pack2(float a, float b) {
    unsigned long long r;
    asm("mov.b64 %0, {%1, %2};" : "=l"(r) : "f"(a), "f"(b));
    return r;
}
__device__ __forceinline__ unsigned long long fma2(unsigned long long a,
                                                   unsigned long long b,
                                                   unsigned long long c) {
    unsigned long long d;
    asm("fma.rn.f32x2 %0, %1, %2, %3;" : "=l"(d) : "l"(a), "l"(b), "l"(c));
    return d;
}
__device__ __forceinline__ float2 unpack2(unsigned long long v) {
    float2 f;
    asm("mov.b64 {%0, %1}, %2;" : "=f"(f.x), "=f"(f.y) : "l"(v));
    return f;
}

// ---------- cp.async helpers ----------
__device__ __forceinline__ void cp4(uint32_t dst, const void* src) {
    asm volatile("cp.async.ca.shared.global [%0], [%1], 4;" :: "r"(dst), "l"(src));
}
__device__ __forceinline__ void cp16(uint32_t dst, const void* src) {
    asm volatile("cp.async.cg.shared.global [%0], [%1], 16;" :: "r"(dst), "l"(src));
}
__device__ __forceinline__ void cp_commit() {
    asm volatile("cp.async.commit_group;");
}
__device__ __forceinline__ void cp_wait1() {
    asm volatile("cp.async.wait_group 1;");
}

// ---------- prep: fold BN params ----------
__global__ void prep_bn(const float* __restrict__ g1, const float* __restrict__ b1,
                        const float* __restrict__ m1, const float* __restrict__ v1,
                        const float* __restrict__ g2, const float* __restrict__ b2,
                        const float* __restrict__ m2, const float* __restrict__ v2) {
    int c = threadIdx.x;
    if (c < CC) {
        float i1 = g1[c] * rsqrtf(v1[c] + EPSV);
        g_s1[c]  = i1;
        g_bb1[c] = b1[c] - m1[c] * i1;
        float i2 = g2[c] * rsqrtf(v2[c] + EPSV);
        g_s2[c]  = i2;
        g_bb2[c] = b2[c] - m2[c] * i2;
    }
}

// ---------- prep: transpose w2 with s2 fold ----------
__global__ void prep_w2t(const float* __restrict__ w2) {
    int i  = blockIdx.x * 256 + threadIdx.x;  // 65536 total
    int co = i >> 8;
    int ci = i & 255;
    g_w2t[ci * 256 + co] = w2[i] * g_s2[co];
}

// ---------- SKA: spatially-varying 3x3 aggregation ----------
// grid (H/2, B*G), block 256: 2 output rows per block.
// Writes raw result (g_ska) and masked+padded result (g_skar).
__global__ void ska_kernel(const float* __restrict__ x, const float* __restrict__ dw,
                           const float* __restrict__ roi) {
    int h0 = blockIdx.x * 2;
    int bg = blockIdx.y;                 // b*G + g
    int b  = bg >> 3, g = bg & 7;
    int tid = threadIdx.x;
    int hr = tid >> 7;                   // 0/1: which output row
    int w  = tid & 127;

    __shared__ float rows[4][130];
    if (tid < 4) {                       // zero halo columns (never overwritten)
        rows[tid][0]   = 0.f;
        rows[tid][129] = 0.f;
    }

    int h = h0 + hr;
    float dwv[9];
    const float* dp = dw + (size_t)bg * 9 * NPIX + h * WW + w;
#pragma unroll
    for (int k = 0; k < 9; ++k) dwv[k] = dp[k * NPIX];

    float rv = roi[b * NPIX + h * WW + w];

    const float* xb = x + (size_t)(b * CC + g * 32) * NPIX;
    float* ob  = g_ska  + (size_t)(b * CC + g * 32) * NPIX + h * WW + w;
    float* obr = g_skar + ((size_t)(b * CC + g * 32) * H2 + h + 1) * W2 + w + 1;

    for (int c = 0; c < 32; ++c) {
        __syncthreads();
        const float* xc = xb + c * NPIX;
#pragma unroll
        for (int j2 = 0; j2 < 2; ++j2) {
            int j  = hr * 2 + j2;        // 0..3
            int hh = h0 - 1 + j;
            rows[j][w + 1] = ((unsigned)hh < (unsigned)HH) ? xc[hh * WW + w] : 0.f;
        }
        __syncthreads();
        float acc = 0.f;
#pragma unroll
        for (int r = 0; r < 3; ++r)
#pragma unroll
            for (int kw = 0; kw < 3; ++kw)
                acc = fmaf(rows[hr + r][w + kw], dwv[r * 3 + kw], acc);
        ob[(size_t)c * NPIX] = acc;
        obr[(size_t)c * H2 * W2] = acc * rv;
    }
}

// ---------- grouped 3x3 conv + BN + ReLU (f32x2, cp.async pipelined) ----------
// grid (8,8,B*8): 16x16 pixel tile, one conv-group (32 in -> 32 out).
// 256 threads: tid>>6 -> 8-cout slab (4 pairs), tid&63 -> 2x2 pixel quad.
__global__ void __launch_bounds__(256, 2)
conv3_kernel(const float* __restrict__ w1) {
    int bz  = blockIdx.z;
    int b   = bz >> 3, vg = bz & 7;
    int px0 = blockIdx.x * 16, py0 = blockIdx.y * 16;
    int tid = threadIdx.x;

    __shared__ float ws2[32 * 9 * 34];   // [cin][tap][co padded to 34]
    __shared__ float xt[2][18][20];      // double-buffered input tile

    // stage weights (coalesced read), fold s1, transposed write
    {
        const float* slab = w1 + vg * 32 * 288;  // w1[(vg*32+co)*288 + k]
        for (int j = tid; j < 9216; j += 256) {
            int co = j / 288;
            int k  = j - co * 288;               // cin*9 + tap
            ws2[k * 34 + co] = slab[j] * g_s1[vg * 32 + co];
        }
    }

    // staging assignment: each thread covers elements tid and tid+256 of 324
    int r0 = tid / 18,          c0 = tid - r0 * 18;
    int i1 = tid + 256;
    int r1 = i1 / 18,           c1 = i1 - r1 * 18;
    bool has1 = (i1 < 324);

    const float* sbase = g_skar + ((size_t)(b * CC + vg * 32) * H2 + py0) * W2 + px0;
    uint32_t xts = (uint32_t)__cvta_generic_to_shared(&xt[0][0][0]);

    auto stage = [&](int buf, int cin) {
        const float* src = sbase + (size_t)cin * H2 * W2;
        uint32_t d = xts + (uint32_t)buf * (18 * 20 * 4);
        cp4(d + (r0 * 20 + c0) * 4, src + r0 * W2 + c0);
        if (has1) cp4(d + (r1 * 20 + c1) * 4, src + r1 * W2 + c1);
    };

    int cog = tid >> 6;          // 0..3 -> cout base cog*8
    int qid = tid & 63;
    int py  = (qid >> 3) * 2;    // 0..14 even
    int px  = (qid & 7) * 2;     // 0..14 even

    unsigned long long acc[4][4]; // [co pair][quad pixel], lanes = {co, co+1}
#pragma unroll
    for (int i = 0; i < 4; ++i)
#pragma unroll
        for (int j = 0; j < 4; ++j) acc[i][j] = 0ull;

    stage(0, 0);
    cp_commit();

    for (int cin = 0; cin < 32; ++cin) {
        int buf = cin & 1;
        __syncthreads();                       // all done reading buf^1
        if (cin + 1 < 32) stage(buf ^ 1, cin + 1);
        cp_commit();                           // (empty group on last iter)
        cp_wait1();                            // current buf complete
        __syncthreads();

        // prepack 4x4 window once
        unsigned long long xp[16];
#pragma unroll
        for (int r = 0; r < 4; ++r)
#pragma unroll
            for (int c = 0; c < 4; ++c) {
                float v = xt[buf][py + r][px + c];
                xp[r * 4 + c] = pack2(v, v);
            }

        const float* wb = ws2 + cin * 9 * 34 + cog * 8;
#pragma unroll
        for (int tap = 0; tap < 9; ++tap) {
            int r = tap / 3, kw = tap - r * 3;
            unsigned long long wv[4];
#pragma unroll
            for (int c2 = 0; c2 < 4; ++c2)
                wv[c2] = *(const unsigned long long*)(wb + tap * 34 + c2 * 2);
#pragma unroll
            for (int c2 = 0; c2 < 4; ++c2) {
                acc[c2][0] = fma2(wv[c2], xp[r * 4 + kw],           acc[c2][0]);
                acc[c2][1] = fma2(wv[c2], xp[r * 4 + kw + 1],       acc[c2][1]);
                acc[c2][2] = fma2(wv[c2], xp[(r + 1) * 4 + kw],     acc[c2][2]);
                acc[c2][3] = fma2(wv[c2], xp[(r + 1) * 4 + kw + 1], acc[c2][3]);
            }
        }
    }

    int hy = py0 + py, wx = px0 + px;
#pragma unroll
    for (int c2 = 0; c2 < 4; ++c2) {
        int cg = vg * 32 + cog * 8 + c2 * 2;
        float bbA = g_bb1[cg], bbB = g_bb1[cg + 1];
#pragma unroll
        for (int i = 0; i < 2; ++i) {
            float2 eA = unpack2(acc[c2][i * 2 + 0]);  // pixel (hy+i, wx)
            float2 eB = unpack2(acc[c2][i * 2 + 1]);  // pixel (hy+i, wx+1)
            float2 rowA = make_float2(fmaxf(eA.x + bbA, 0.f), fmaxf(eB.x + bbA, 0.f));
            float2 rowB = make_float2(fmaxf(eA.y + bbB, 0.f), fmaxf(eB.y + bbB, 0.f));
            size_t oa = (size_t)(b * CC + cg) * NPIX + (hy + i) * WW + wx;
            *(float2*)(g_t + oa)        = rowA;
            *(float2*)(g_t + oa + NPIX) = rowB;
        }
    }
}

// ---------- 1x1 conv (GEMM) + BN + residual (f32x2, cp.async pipelined) ----------
// grid (128, 2, B): 128 px x 128 co tile. 256 threads: 8 co x 8 px per thread.
__global__ void __launch_bounds__(256, 2)
conv1x1_kernel(float* __restrict__ out) {
    int p0  = blockIdx.x * 128;
    int co0 = blockIdx.y * 128;
    int b   = blockIdx.z;
    int tid = threadIdx.x;
    int tx  = tid & 15;   // px direction (8 px each)
    int ty  = tid >> 4;   // co direction (8 co each)

    __shared__ float As[2][16][128];  // w2t[k][co]  (s2 folded)
    __shared__ float Bs[2][16][128];  // t[k][p]

    unsigned long long acc[4][8];  // [co pair][px], lanes = {co, co+1}
#pragma unroll
    for (int i = 0; i < 4; ++i)
#pragma unroll
        for (int j = 0; j < 8; ++j) acc[i][j] = 0ull;

    const float* tb = g_t + (size_t)b * CC * NPIX;

    // 16B-chunk staging: 512 chunks each for As/Bs; thread does chunks tid, tid+256
    uint32_t as_s = (uint32_t)__cvta_generic_to_shared(&As[0][0][0]);
    uint32_t bs_s = (uint32_t)__cvta_generic_to_shared(&Bs[0][0][0]);

    auto stage = [&](int buf, int kb) {
        uint32_t da = as_s + (uint32_t)buf * (16 * 128 * 4);
        uint32_t db = bs_s + (uint32_t)buf * (16 * 128 * 4);
#pragma unroll
        for (int rep = 0; rep < 2; ++rep) {
            int ch  = tid + rep * 256;
            int kk  = ch >> 5;
            int col = (ch & 31) * 4;
            int krow = kb * 16 + kk;
            cp16(da + (kk * 128 + col) * 4, g_w2t + krow * 256 + co0 + col);
            cp16(db + (kk * 128 + col) * 4, tb + (size_t)krow * NPIX + p0 + col);
        }
    };

    stage(0, 0);
    cp_commit();

    for (int kb = 0; kb < 16; ++kb) {
        int buf = kb & 1;
        __syncthreads();
        if (kb + 1 < 16) stage(buf ^ 1, kb + 1);
        cp_commit();
        cp_wait1();
        __syncthreads();
#pragma unroll
        for (int kk = 0; kk < 16; ++kk) {
            const float4* bp4 = (const float4*)&Bs[buf][kk][tx * 8];
            float4 b0 = bp4[0], b1 = bp4[1];
            unsigned long long bp[8];
            bp[0] = pack2(b0.x, b0.x); bp[1] = pack2(b0.y, b0.y);
            bp[2] = pack2(b0.z, b0.z); bp[3] = pack2(b0.w, b0.w);
            bp[4] = pack2(b1.x, b1.x); bp[5] = pack2(b1.y, b1.y);
            bp[6] = pack2(b1.z, b1.z); bp[7] = pack2(b1.w, b1.w);
            const float* ar = &As[buf][kk][ty * 8];
#pragma unroll
            for (int c2 = 0; c2 < 4; ++c2) {
                unsigned long long wv = *(const unsigned long long*)(ar + c2 * 2);
#pragma unroll
                for (int j = 0; j < 8; ++j)
                    acc[c2][j] = fma2(wv, bp[j], acc[c2][j]);
            }
        }
    }

    // epilogue: out = ska + dot + bb2
#pragma unroll
    for (int c2 = 0; c2 < 4; ++c2) {
        int co = co0 + ty * 8 + c2 * 2;
        float bbA = g_bb2[co], bbB = g_bb2[co + 1];
        float2 f[8];
#pragma unroll
        for (int j = 0; j < 8; ++j) f[j] = unpack2(acc[c2][j]);
        size_t i0 = (size_t)(b * CC + co) * NPIX + p0 + tx * 8;
        float4 sA0 = *(const float4*)(g_ska + i0);
        float4 sA1 = *(const float4*)(g_ska + i0 + 4);
        float4 sB0 = *(const float4*)(g_ska + i0 + NPIX);
        float4 sB1 = *(const float4*)(g_ska + i0 + NPIX + 4);
        float4 oA0 = make_float4(sA0.x + f[0].x + bbA, sA0.y + f[1].x + bbA,
                                 sA0.z + f[2].x + bbA, sA0.w + f[3].x + bbA);
        float4 oA1 = make_float4(sA1.x + f[4].x + bbA, sA1.y + f[5].x + bbA,
                                 sA1.z + f[6].x + bbA, sA1.w + f[7].x + bbA);
        float4 oB0 = make_float4(sB0.x + f[0].y + bbB, sB0.y + f[1].y + bbB,
                                 sB0.z + f[2].y + bbB, sB0.w + f[3].y + bbB);
        float4 oB1 = make_float4(sB1.x + f[4].y + bbB, sB1.y + f[5].y + bbB,
                                 sB1.z + f[6].y + bbB, sB1.w + f[7].y + bbB);
        *(float4*)(out + i0)            = oA0;
        *(float4*)(out + i0 + 4)        = oA1;
        *(float4*)(out + i0 + NPIX)     = oB0;
        *(float4*)(out + i0 + NPIX + 4) = oB1;
    }
}

extern "C" void kernel_launch(void* const* d_in, const int* in_sizes, int n_in,
                              void* d_out, int out_size) {
    const float* x   = (const float*)d_in[0];
    const float* dw  = (const float*)d_in[1];
    const float* roi = (const float*)d_in[2];
    const float* w1  = (const float*)d_in[3];
    const float* g1  = (const float*)d_in[4];
    const float* b1  = (const float*)d_in[5];
    const float* m1  = (const float*)d_in[6];
    const float* v1  = (const float*)d_in[7];
    const float* w2  = (const float*)d_in[8];
    const float* g2  = (const float*)d_in[9];
    const float* b2  = (const float*)d_in[10];
    const float* m2  = (const float*)d_in[11];
    const float* v2  = (const float*)d_in[12];
    float* out = (float*)d_out;

    prep_bn<<<1, 256>>>(g1, b1, m1, v1, g2, b2, m2, v2);
    prep_w2t<<<256, 256>>>(w2);
    ska_kernel<<<dim3(HH / 2, BB * GG), 256>>>(x, dw, roi);
    conv3_kernel<<<dim3(8, 8, BB * 8), 256>>>(w1);
    conv1x1_kernel<<<dim3(128, 2, BB), 256>>>(out);
}

// round 6
// speedup vs baseline: 1.4854x; 1.1088x over previous
#include <cuda_runtime.h>
#include <cuda_bf16.h>
#include <cstdint>

// Problem constants
#define BB   8
#define CC   256
#define HH   128
#define WW   128
#define GG   8       // ska groups (32 ch each)
#define NPIX 16384   // H*W
#define EPSV 1e-5f
#define H2   130     // padded rows
#define W2   132     // padded cols (16B-friendly)

// Scratch (device globals; allocation-free rule). Zero-initialized at load:
// g_skar's 1-pixel border is never written -> stays zero (implicit padding).
__device__ float g_ska[BB * CC * NPIX];       // raw SKA output (residual), planar
__device__ float g_skar[BB * CC * H2 * W2];   // ska*roi, zero-padded (conv3 input)
__device__ float g_t2[BB * NPIX * CC];        // after conv3x3+BN+ReLU, [b][pix][ci] (tf32-rounded)
__device__ float g_w2s[CC * CC];              // w2 with s2 folded, [co][ci] (tf32-rounded)
__device__ float g_s1[CC], g_bb1[CC], g_s2[CC], g_bb2[CC];

// ---------- packed f32x2 helpers ----------
__device__ __forceinline__ unsigned long long pack2(float a, float b) {
    unsigned long long r;
    asm("mov.b64 %0, {%1, %2};" : "=l"(r) : "f"(a), "f"(b));
    return r;
}
__device__ __forceinline__ unsigned long long fma2(unsigned long long a,
                                                   unsigned long long b,
                                                   unsigned long long c) {
    unsigned long long d;
    asm("fma.rn.f32x2 %0, %1, %2, %3;" : "=l"(d) : "l"(a), "l"(b), "l"(c));
    return d;
}
__device__ __forceinline__ float2 unpack2(unsigned long long v) {
    float2 f;
    asm("mov.b64 {%0, %1}, %2;" : "=f"(f.x), "=f"(f.y) : "l"(v));
    return f;
}

// ---------- cp.async helpers ----------
__device__ __forceinline__ void cp4(uint32_t dst, const void* src) {
    asm volatile("cp.async.ca.shared.global [%0], [%1], 4;" :: "r"(dst), "l"(src));
}
__device__ __forceinline__ void cp16(uint32_t dst, const void* src) {
    asm volatile("cp.async.cg.shared.global [%0], [%1], 16;" :: "r"(dst), "l"(src));
}
__device__ __forceinline__ void cp_commit() {
    asm volatile("cp.async.commit_group;");
}
__device__ __forceinline__ void cp_wait1() {
    asm volatile("cp.async.wait_group 1;");
}

__device__ __forceinline__ uint32_t smem_u32(const void* p) {
    uint32_t a;
    asm("{ .reg .u64 t; cvta.to.shared.u64 t, %1; cvt.u32.u64 %0, t; }" : "=r"(a) : "l"(p));
    return a;
}

// ---------- tf32 round-to-nearest ----------
__device__ __forceinline__ float to_tf32(float x) {
    uint32_t u;
    asm("cvt.rna.tf32.f32 %0, %1;" : "=r"(u) : "f"(x));
    return __uint_as_float(u);
}

// ---------- mma.sync m16n8k8 tf32 ----------
__device__ __forceinline__ void mma8(float* c, const uint32_t* a, const uint32_t* b) {
    asm volatile(
        "mma.sync.aligned.m16n8k8.row.col.f32.tf32.tf32.f32 "
        "{%0,%1,%2,%3}, {%4,%5,%6,%7}, {%8,%9}, {%0,%1,%2,%3};"
        : "+f"(c[0]), "+f"(c[1]), "+f"(c[2]), "+f"(c[3])
        : "r"(a[0]), "r"(a[1]), "r"(a[2]), "r"(a[3]), "r"(b[0]), "r"(b[1]));
}

// ---------- prep: fold BN params ----------
__global__ void prep_bn(const float* __restrict__ g1, const float* __restrict__ b1,
                        const float* __restrict__ m1, const float* __restrict__ v1,
                        const float* __restrict__ g2, const float* __restrict__ b2,
                        const float* __restrict__ m2, const float* __restrict__ v2) {
    int c = threadIdx.x;
    if (c < CC) {
        float i1 = g1[c] * rsqrtf(v1[c] + EPSV);
        g_s1[c]  = i1;
        g_bb1[c] = b1[c] - m1[c] * i1;
        float i2 = g2[c] * rsqrtf(v2[c] + EPSV);
        g_s2[c]  = i2;
        g_bb2[c] = b2[c] - m2[c] * i2;
    }
}

// ---------- prep: fold s2 into w2, round to tf32 ([co][ci] K-major) ----------
__global__ void prep_w2s(const float* __restrict__ w2) {
    int i  = blockIdx.x * 256 + threadIdx.x;  // 65536 total
    g_w2s[i] = to_tf32(w2[i] * g_s2[i >> 8]);
}

// ---------- SKA: spatially-varying 3x3 aggregation ----------
__global__ void ska_kernel(const float* __restrict__ x, const float* __restrict__ dw,
                           const float* __restrict__ roi) {
    int h0 = blockIdx.x * 2;
    int bg = blockIdx.y;                 // b*G + g
    int b  = bg >> 3, g = bg & 7;
    int tid = threadIdx.x;
    int hr = tid >> 7;                   // 0/1: which output row
    int w  = tid & 127;

    __shared__ float rows[4][130];
    if (tid < 4) {
        rows[tid][0]   = 0.f;
        rows[tid][129] = 0.f;
    }

    int h = h0 + hr;
    float dwv[9];
    const float* dp = dw + (size_t)bg * 9 * NPIX + h * WW + w;
#pragma unroll
    for (int k = 0; k < 9; ++k) dwv[k] = dp[k * NPIX];

    float rv = roi[b * NPIX + h * WW + w];

    const float* xb = x + (size_t)(b * CC + g * 32) * NPIX;
    float* ob  = g_ska  + (size_t)(b * CC + g * 32) * NPIX + h * WW + w;
    float* obr = g_skar + ((size_t)(b * CC + g * 32) * H2 + h + 1) * W2 + w + 1;

    for (int c = 0; c < 32; ++c) {
        __syncthreads();
        const float* xc = xb + c * NPIX;
#pragma unroll
        for (int j2 = 0; j2 < 2; ++j2) {
            int j  = hr * 2 + j2;
            int hh = h0 - 1 + j;
            rows[j][w + 1] = ((unsigned)hh < (unsigned)HH) ? xc[hh * WW + w] : 0.f;
        }
        __syncthreads();
        float acc = 0.f;
#pragma unroll
        for (int r = 0; r < 3; ++r)
#pragma unroll
            for (int kw = 0; kw < 3; ++kw)
                acc = fmaf(rows[hr + r][w + kw], dwv[r * 3 + kw], acc);
        ob[(size_t)c * NPIX] = acc;
        obr[(size_t)c * H2 * W2] = acc * rv;
    }
}

// ---------- grouped 3x3 conv + BN + ReLU (f32x2, cp.async pipelined) ----------
// Output written to g_t2 in [pix][ci] layout (tf32-rounded) via smem transpose.
__global__ void __launch_bounds__(256, 2)
conv3_kernel(const float* __restrict__ w1) {
    int bz  = blockIdx.z;
    int b   = bz >> 3, vg = bz & 7;
    int px0 = blockIdx.x * 16, py0 = blockIdx.y * 16;
    int tid = threadIdx.x;

    __shared__ float ws2[32 * 9 * 34];   // weights; reused as transpose buffer
    __shared__ float xt[2][18][20];

    {
        const float* slab = w1 + vg * 32 * 288;
        for (int j = tid; j < 9216; j += 256) {
            int co = j / 288;
            int k  = j - co * 288;
            ws2[k * 34 + co] = slab[j] * g_s1[vg * 32 + co];
        }
    }

    int r0 = tid / 18,          c0 = tid - r0 * 18;
    int i1 = tid + 256;
    int r1 = i1 / 18,           c1 = i1 - r1 * 18;
    bool has1 = (i1 < 324);

    const float* sbase = g_skar + ((size_t)(b * CC + vg * 32) * H2 + py0) * W2 + px0;
    uint32_t xts = smem_u32(&xt[0][0][0]);

    auto stage = [&](int buf, int cin) {
        const float* src = sbase + (size_t)cin * H2 * W2;
        uint32_t d = xts + (uint32_t)buf * (18 * 20 * 4);
        cp4(d + (r0 * 20 + c0) * 4, src + r0 * W2 + c0);
        if (has1) cp4(d + (r1 * 20 + c1) * 4, src + r1 * W2 + c1);
    };

    int cog = tid >> 6;
    int qid = tid & 63;
    int py  = (qid >> 3) * 2;
    int px  = (qid & 7) * 2;

    unsigned long long acc[4][4];
#pragma unroll
    for (int i = 0; i < 4; ++i)
#pragma unroll
        for (int j = 0; j < 4; ++j) acc[i][j] = 0ull;

    stage(0, 0);
    cp_commit();

    for (int cin = 0; cin < 32; ++cin) {
        int buf = cin & 1;
        __syncthreads();
        if (cin + 1 < 32) stage(buf ^ 1, cin + 1);
        cp_commit();
        cp_wait1();
        __syncthreads();

        unsigned long long xp[16];
#pragma unroll
        for (int r = 0; r < 4; ++r)
#pragma unroll
            for (int c = 0; c < 4; ++c) {
                float v = xt[buf][py + r][px + c];
                xp[r * 4 + c] = pack2(v, v);
            }

        const float* wb = ws2 + cin * 9 * 34 + cog * 8;
#pragma unroll
        for (int tap = 0; tap < 9; ++tap) {
            int r = tap / 3, kw = tap - r * 3;
            unsigned long long wv[4];
#pragma unroll
            for (int c2 = 0; c2 < 4; ++c2)
                wv[c2] = *(const unsigned long long*)(wb + tap * 34 + c2 * 2);
#pragma unroll
            for (int c2 = 0; c2 < 4; ++c2) {
                acc[c2][0] = fma2(wv[c2], xp[r * 4 + kw],           acc[c2][0]);
                acc[c2][1] = fma2(wv[c2], xp[r * 4 + kw + 1],       acc[c2][1]);
                acc[c2][2] = fma2(wv[c2], xp[(r + 1) * 4 + kw],     acc[c2][2]);
                acc[c2][3] = fma2(wv[c2], xp[(r + 1) * 4 + kw + 1], acc[c2][3]);
            }
        }
    }

    // epilogue: BN+ReLU, tf32 round, transpose via smem, write g_t2[pix][ci]
    __syncthreads();   // done with weights
#pragma unroll
    for (int c2 = 0; c2 < 4; ++c2) {
        int col = cog * 8 + c2 * 2;
        int cg  = vg * 32 + col;
        float bbA = g_bb1[cg], bbB = g_bb1[cg + 1];
#pragma unroll
        for (int i = 0; i < 2; ++i)
#pragma unroll
            for (int j = 0; j < 2; ++j) {
                float2 e = unpack2(acc[c2][i * 2 + j]);
                int lp = (py + i) * 16 + (px + j);
                ws2[lp * 33 + col]     = to_tf32(fmaxf(e.x + bbA, 0.f));
                ws2[lp * 33 + col + 1] = to_tf32(fmaxf(e.y + bbB, 0.f));
            }
    }
    __syncthreads();
    {
        int lp = tid;                       // local pixel 0..255
        int gp = (py0 + (lp >> 4)) * WW + px0 + (lp & 15);
        float* o = g_t2 + ((size_t)b * NPIX + gp) * CC + vg * 32;
        const float* s = ws2 + lp * 33;
#pragma unroll
        for (int q = 0; q < 8; ++q) {
            float4 v = make_float4(s[q * 4], s[q * 4 + 1], s[q * 4 + 2], s[q * 4 + 3]);
            *(float4*)(o + q * 4) = v;
        }
    }
}

// ---------- 1x1 conv: mma.sync tf32 GEMM + BN + residual ----------
// grid (128, 2, B): block = 128 pix x 128 co, K=256 (8 chunks of 32).
// 8 warps: warp = 32 pix x 64 co = 2 m-tiles x 8 n-tiles of m16n8k8.
// Dynamic smem: A[2][128][36], B[2][128][36] floats = 73728 B.
#define CSTR  36
#define SMA1  (128 * CSTR * 4)          // 18432
#define SMB0  (2 * SMA1)                // 36864
#define SM1X1 (4 * SMA1)                // 73728

__global__ void __launch_bounds__(256, 2)
conv1x1_mma(float* __restrict__ out) {
    extern __shared__ float sm[];
    uint32_t ss = smem_u32(sm);
    int tid  = threadIdx.x;
    int wid  = tid >> 5, lane = tid & 31;
    int p0   = blockIdx.x * 128;
    int co0  = blockIdx.y * 128;
    int b    = blockIdx.z;

    int pm = (wid & 3) * 32;    // warp pixel base (2 m-tiles)
    int cn = (wid >> 2) * 64;   // warp cout base (8 n-tiles)
    int rr = lane >> 2, q = lane & 3;

    const float* abase = g_t2 + ((size_t)b * NPIX + p0) * CC;
    const float* wbase = g_w2s + (size_t)co0 * CC;

    auto stage = [&](int buf, int kb) {
        uint32_t da = ss + (uint32_t)buf * SMA1;
        uint32_t db = ss + SMB0 + (uint32_t)buf * SMA1;
#pragma unroll
        for (int j = 0; j < 4; ++j) {
            int ch  = tid + j * 256;          // 0..1023
            int row = ch >> 3, c16 = ch & 7;  // row 0..127, 16B-chunk 0..7
            uint32_t doff = (uint32_t)(row * (CSTR * 4) + c16 * 16);
            const float* asrc = abase + (size_t)row * CC + kb * 32 + c16 * 4;
            const float* bsrc = wbase + (size_t)row * CC + kb * 32 + c16 * 4;
            cp16(da + doff, asrc);
            cp16(db + doff, bsrc);
        }
    };

    float acc[8][2][4];
#pragma unroll
    for (int nt = 0; nt < 8; ++nt)
#pragma unroll
        for (int mt = 0; mt < 2; ++mt)
#pragma unroll
            for (int i = 0; i < 4; ++i) acc[nt][mt][i] = 0.f;

    stage(0, 0);
    cp_commit();

    for (int kb = 0; kb < 8; ++kb) {
        int buf = kb & 1;
        __syncthreads();
        if (kb + 1 < 8) stage(buf ^ 1, kb + 1);
        cp_commit();
        cp_wait1();
        __syncthreads();

        const float* Ab = sm + buf * (128 * CSTR);
        const float* Bb = sm + 2 * (128 * CSTR) + buf * (128 * CSTR);

#pragma unroll
        for (int ks = 0; ks < 4; ++ks) {
            int k0 = ks * 8;
            uint32_t afr[2][4], bfr[8][2];
#pragma unroll
            for (int mt = 0; mt < 2; ++mt) {
                const float* p = Ab + (pm + mt * 16 + rr) * CSTR + k0 + q;
                afr[mt][0] = __float_as_uint(p[0]);
                afr[mt][1] = __float_as_uint(p[8 * CSTR]);
                afr[mt][2] = __float_as_uint(p[4]);
                afr[mt][3] = __float_as_uint(p[8 * CSTR + 4]);
            }
#pragma unroll
            for (int nt = 0; nt < 8; ++nt) {
                const float* p = Bb + (cn + nt * 8 + rr) * CSTR + k0 + q;
                bfr[nt][0] = __float_as_uint(p[0]);
                bfr[nt][1] = __float_as_uint(p[4]);
            }
#pragma unroll
            for (int nt = 0; nt < 8; ++nt)
#pragma unroll
                for (int mt = 0; mt < 2; ++mt)
                    mma8(acc[nt][mt], afr[mt], bfr[nt]);
        }
    }

    // epilogue: out = ska + D + bb2  (planar [co][pix])
    int q2 = q * 2;
#pragma unroll
    for (int nt = 0; nt < 8; ++nt) {
        int co = co0 + cn + nt * 8 + q2;
        float bbA = g_bb2[co], bbB = g_bb2[co + 1];
#pragma unroll
        for (int mt = 0; mt < 2; ++mt) {
            int pix = p0 + pm + mt * 16 + rr;
            size_t a0 = (size_t)(b * CC + co) * NPIX + pix;
            size_t a1 = a0 + NPIX;          // co+1
            out[a0]     = g_ska[a0]     + acc[nt][mt][0] + bbA;
            out[a1]     = g_ska[a1]     + acc[nt][mt][1] + bbB;
            out[a0 + 8] = g_ska[a0 + 8] + acc[nt][mt][2] + bbA;
            out[a1 + 8] = g_ska[a1 + 8] + acc[nt][mt][3] + bbB;
        }
    }
}

extern "C" void kernel_launch(void* const* d_in, const int* in_sizes, int n_in,
                              void* d_out, int out_size) {
    const float* x   = (const float*)d_in[0];
    const float* dw  = (const float*)d_in[1];
    const float* roi = (const float*)d_in[2];
    const float* w1  = (const float*)d_in[3];
    const float* g1  = (const float*)d_in[4];
    const float* b1  = (const float*)d_in[5];
    const float* m1  = (const float*)d_in[6];
    const float* v1  = (const float*)d_in[7];
    const float* w2  = (const float*)d_in[8];
    const float* g2  = (const float*)d_in[9];
    const float* b2  = (const float*)d_in[10];
    const float* m2  = (const float*)d_in[11];
    const float* v2  = (const float*)d_in[12];
    float* out = (float*)d_out;

    cudaFuncSetAttribute(conv1x1_mma, cudaFuncAttributeMaxDynamicSharedMemorySize, SM1X1);

    prep_bn<<<1, 256>>>(g1, b1, m1, v1, g2, b2, m2, v2);
    prep_w2s<<<256, 256>>>(w2);
    ska_kernel<<<dim3(HH / 2, BB * GG), 256>>>(x, dw, roi);
    conv3_kernel<<<dim3(8, 8, BB * 8), 256>>>(w1);
    conv1x1_mma<<<dim3(128, 2, BB), 256, SM1X1>>>(out);
}

// round 7
// speedup vs baseline: 2.3485x; 1.5810x over previous
#include <cuda_runtime.h>
#include <cuda_bf16.h>
#include <cstdint>

// Problem constants
#define BB   8
#define CC   256
#define HH   128
#define WW   128
#define GG   8       // ska groups (32 ch each)
#define NPIX 16384   // H*W
#define EPSV 1e-5f
#define HP   130     // spatially padded dim (1-px zero border)

// Scratch (device globals; allocation-free rule). Zero-initialized at load:
// g_ska2's 1-pixel spatial border is never written -> stays zero (implicit pad).
__device__ float g_ska[BB * CC * NPIX];                 // raw SKA output (residual), planar
__device__ float g_ska2[BB * GG * HP * HP * 32];        // ska*roi, channel-last, padded, tf32
__device__ float g_t2[BB * NPIX * CC];                  // conv3 out, [b][pix][ci], tf32
__device__ float g_w2s[CC * CC];                        // w2 with s2 folded, [co][ci], tf32
__device__ float g_s1[CC], g_bb1[CC], g_s2[CC], g_bb2[CC];

// ---------- cp.async helpers ----------
__device__ __forceinline__ void cp16(uint32_t dst, const void* src) {
    asm volatile("cp.async.cg.shared.global [%0], [%1], 16;" :: "r"(dst), "l"(src));
}
__device__ __forceinline__ void cp_commit() {
    asm volatile("cp.async.commit_group;");
}
__device__ __forceinline__ void cp_wait1() {
    asm volatile("cp.async.wait_group 1;");
}
__device__ __forceinline__ void cp_wait0() {
    asm volatile("cp.async.wait_group 0;");
}

__device__ __forceinline__ uint32_t smem_u32(const void* p) {
    uint32_t a;
    asm("{ .reg .u64 t; cvta.to.shared.u64 t, %1; cvt.u32.u64 %0, t; }" : "=r"(a) : "l"(p));
    return a;
}

// ---------- tf32 round-to-nearest ----------
__device__ __forceinline__ float to_tf32(float x) {
    uint32_t u;
    asm("cvt.rna.tf32.f32 %0, %1;" : "=r"(u) : "f"(x));
    return __uint_as_float(u);
}

// ---------- mma.sync m16n8k8 tf32 ----------
__device__ __forceinline__ void mma8(float* c, const uint32_t* a, const uint32_t* b) {
    asm volatile(
        "mma.sync.aligned.m16n8k8.row.col.f32.tf32.tf32.f32 "
        "{%0,%1,%2,%3}, {%4,%5,%6,%7}, {%8,%9}, {%0,%1,%2,%3};"
        : "+f"(c[0]), "+f"(c[1]), "+f"(c[2]), "+f"(c[3])
        : "r"(a[0]), "r"(a[1]), "r"(a[2]), "r"(a[3]), "r"(b[0]), "r"(b[1]));
}

// ---------- prep: fold BN params ----------
__global__ void prep_bn(const float* __restrict__ g1, const float* __restrict__ b1,
                        const float* __restrict__ m1, const float* __restrict__ v1,
                        const float* __restrict__ g2, const float* __restrict__ b2,
                        const float* __restrict__ m2, const float* __restrict__ v2) {
    int c = threadIdx.x;
    if (c < CC) {
        float i1 = g1[c] * rsqrtf(v1[c] + EPSV);
        g_s1[c]  = i1;
        g_bb1[c] = b1[c] - m1[c] * i1;
        float i2 = g2[c] * rsqrtf(v2[c] + EPSV);
        g_s2[c]  = i2;
        g_bb2[c] = b2[c] - m2[c] * i2;
    }
}

// ---------- prep: fold s2 into w2, round to tf32 ([co][ci] K-major) ----------
__global__ void prep_w2s(const float* __restrict__ w2) {
    int i  = blockIdx.x * 256 + threadIdx.x;  // 65536 total
    g_w2s[i] = to_tf32(w2[i] * g_s2[i >> 8]);
}

// ---------- SKA: spatially-varying 3x3 aggregation ----------
// grid (H/2, B*G), block 256: 2 output rows. Writes planar g_ska (residual)
// and channel-last padded g_ska2 (conv3 MMA input, tf32-rounded) from registers.
__global__ void ska_kernel(const float* __restrict__ x, const float* __restrict__ dw,
                           const float* __restrict__ roi) {
    int h0 = blockIdx.x * 2;
    int bg = blockIdx.y;                 // b*G + g
    int b  = bg >> 3, g = bg & 7;
    int tid = threadIdx.x;
    int hr = tid >> 7;                   // 0/1: which output row
    int w  = tid & 127;

    __shared__ float rows[4][130];
    if (tid < 4) {
        rows[tid][0]   = 0.f;
        rows[tid][129] = 0.f;
    }

    int h = h0 + hr;
    float dwv[9];
    const float* dp = dw + (size_t)bg * 9 * NPIX + h * WW + w;
#pragma unroll
    for (int k = 0; k < 9; ++k) dwv[k] = dp[k * NPIX];

    float rv = roi[b * NPIX + h * WW + w];

    const float* xb = x + (size_t)(b * CC + g * 32) * NPIX;
    float* ob = g_ska + (size_t)(b * CC + g * 32) * NPIX + h * WW + w;

    float vals[32];
#pragma unroll
    for (int c = 0; c < 32; ++c) {
        __syncthreads();
        const float* xc = xb + c * NPIX;
#pragma unroll
        for (int j2 = 0; j2 < 2; ++j2) {
            int j  = hr * 2 + j2;
            int hh = h0 - 1 + j;
            rows[j][w + 1] = ((unsigned)hh < (unsigned)HH) ? xc[hh * WW + w] : 0.f;
        }
        __syncthreads();
        float acc = 0.f;
#pragma unroll
        for (int r = 0; r < 3; ++r)
#pragma unroll
            for (int kw = 0; kw < 3; ++kw)
                acc = fmaf(rows[hr + r][w + kw], dwv[r * 3 + kw], acc);
        ob[(size_t)c * NPIX] = acc;
        vals[c] = to_tf32(acc * rv);
    }

    // channel-last padded write (interior only; border stays zero)
    float* o = g_ska2 + (((size_t)(b * GG + g) * HP + h + 1) * HP + (w + 1)) * 32;
#pragma unroll
    for (int qq = 0; qq < 8; ++qq)
        ((float4*)o)[qq] = make_float4(vals[qq * 4], vals[qq * 4 + 1],
                                       vals[qq * 4 + 2], vals[qq * 4 + 3]);
}

// ---------- grouped 3x3 conv: mma.sync tf32 + BN + ReLU ----------
// grid (8,8,64): CTA = 16x16 pixel tile, one (b, group). K=288 fully smem-resident.
// 8 warps: warp = 2 pixel rows (m16 = 16 px of one row) x all 32 couts (4 n-tiles).
// Dyn smem: tile[324][36] (18x18 px, ch padded 36) + wt[9][32][36].
#define C3_TILE_F  (324 * 36)            // 11664 floats
#define C3_WT_F    (9 * 32 * 36)         // 10368 floats
#define C3_SMEM    ((C3_TILE_F + C3_WT_F) * 4)   // 88128 B

__global__ void __launch_bounds__(256, 2)
conv3_mma(const float* __restrict__ w1) {
    extern __shared__ float dsm[];
    float* tile = dsm;                   // [pix(18x18)][36]
    float* wt   = dsm + C3_TILE_F;       // [tap][co][36]

    int bz  = blockIdx.z;
    int b   = bz >> 3, g = bz & 7;
    int px0 = blockIdx.x * 16, py0 = blockIdx.y * 16;
    int tid = threadIdx.x;
    int wid = tid >> 5, lane = tid & 31;
    int rr  = lane >> 2, q = lane & 3;

    // stage input tile via cp.async: 324 pixels x 8 x 16B chunks
    {
        const float* sbase = g_ska2 + (((size_t)(b * GG + g) * HP + py0) * HP + px0) * 32;
        uint32_t ts = smem_u32(tile);
        for (int ch = tid; ch < 2592; ch += 256) {
            int pix = ch >> 3, c16 = ch & 7;
            int r = pix / 18, c = pix - r * 18;
            cp16(ts + (uint32_t)(pix * 144 + c16 * 16),
                 sbase + ((size_t)r * HP + c) * 32 + c16 * 4);
        }
        cp_commit();
    }

    // stage weights: w1[(g*32+co)*288 + cin*9 + tap] * s1 -> wt[tap][co][cin]
    {
        const float* slab = w1 + g * 32 * 288;
        float s;
        for (int j = tid; j < 9216; j += 256) {
            int co  = j / 288;
            int k   = j - co * 288;
            int cin = k / 9, tap = k - cin * 9;
            s = to_tf32(slab[j] * g_s1[g * 32 + co]);
            wt[(tap * 32 + co) * 36 + cin] = s;
        }
    }

    float acc[2][4][4];
#pragma unroll
    for (int mt = 0; mt < 2; ++mt)
#pragma unroll
        for (int nt = 0; nt < 4; ++nt)
#pragma unroll
            for (int i = 0; i < 4; ++i) acc[mt][nt][i] = 0.f;

    cp_wait0();
    __syncthreads();

#pragma unroll
    for (int tap = 0; tap < 9; ++tap) {
        int kh = tap / 3, kw = tap - kh * 3;
        const float* wtp = wt + tap * (32 * 36);
#pragma unroll
        for (int ks = 0; ks < 4; ++ks) {
            int k0 = ks * 8;
            uint32_t afr[2][4];
#pragma unroll
            for (int mt = 0; mt < 2; ++mt) {
                int r_t = wid * 2 + mt + kh;                 // tile row
                const float* p = tile + (r_t * 18 + kw + rr) * 36 + k0 + q;
                afr[mt][0] = __float_as_uint(p[0]);
                afr[mt][1] = __float_as_uint(p[8 * 36]);
                afr[mt][2] = __float_as_uint(p[4]);
                afr[mt][3] = __float_as_uint(p[8 * 36 + 4]);
            }
            uint32_t bfr[4][2];
#pragma unroll
            for (int nt = 0; nt < 4; ++nt) {
                const float* p = wtp + (nt * 8 + rr) * 36 + k0 + q;
                bfr[nt][0] = __float_as_uint(p[0]);
                bfr[nt][1] = __float_as_uint(p[4]);
            }
#pragma unroll
            for (int mt = 0; mt < 2; ++mt)
#pragma unroll
                for (int nt = 0; nt < 4; ++nt)
                    mma8(acc[mt][nt], afr[mt], bfr[nt]);
        }
    }

    // epilogue: BN + ReLU + tf32 round, write g_t2 [b][pix][ci] (channel-last)
    int q2 = q * 2;
#pragma unroll
    for (int mt = 0; mt < 2; ++mt) {
        int y = py0 + wid * 2 + mt;
        size_t prow = (size_t)b * NPIX + y * WW;
#pragma unroll
        for (int nt = 0; nt < 4; ++nt) {
            int cg = g * 32 + nt * 8 + q2;
            float bbA = g_bb1[cg], bbB = g_bb1[cg + 1];
            float* o0 = g_t2 + (prow + px0 + rr) * CC + cg;
            float* o1 = g_t2 + (prow + px0 + rr + 8) * CC + cg;
            float2 v0 = make_float2(to_tf32(fmaxf(acc[mt][nt][0] + bbA, 0.f)),
                                    to_tf32(fmaxf(acc[mt][nt][1] + bbB, 0.f)));
            float2 v1 = make_float2(to_tf32(fmaxf(acc[mt][nt][2] + bbA, 0.f)),
                                    to_tf32(fmaxf(acc[mt][nt][3] + bbB, 0.f)));
            *(float2*)o0 = v0;
            *(float2*)o1 = v1;
        }
    }
}

// ---------- 1x1 conv: mma.sync tf32 GEMM + BN + residual ----------
// grid (128, 2, B): block = 128 pix x 128 co, K=256 (8 chunks of 32).
// 8 warps: warp = 32 pix x 64 co = 2 m-tiles x 8 n-tiles of m16n8k8.
#define CSTR  36
#define SMA1  (128 * CSTR * 4)          // 18432
#define SMB0  (2 * SMA1)                // 36864
#define SM1X1 (4 * SMA1)                // 73728

__global__ void __launch_bounds__(256, 2)
conv1x1_mma(float* __restrict__ out) {
    extern __shared__ float sm[];
    uint32_t ss = smem_u32(sm);
    int tid  = threadIdx.x;
    int wid  = tid >> 5, lane = tid & 31;
    int p0   = blockIdx.x * 128;
    int co0  = blockIdx.y * 128;
    int b    = blockIdx.z;

    int pm = (wid & 3) * 32;    // warp pixel base (2 m-tiles)
    int cn = (wid >> 2) * 64;   // warp cout base (8 n-tiles)
    int rr = lane >> 2, q = lane & 3;

    const float* abase = g_t2 + ((size_t)b * NPIX + p0) * CC;
    const float* wbase = g_w2s + (size_t)co0 * CC;

    auto stage = [&](int buf, int kb) {
        uint32_t da = ss + (uint32_t)buf * SMA1;
        uint32_t db = ss + SMB0 + (uint32_t)buf * SMA1;
#pragma unroll
        for (int j = 0; j < 4; ++j) {
            int ch  = tid + j * 256;          // 0..1023
            int row = ch >> 3, c16 = ch & 7;  // row 0..127, 16B-chunk 0..7
            uint32_t doff = (uint32_t)(row * (CSTR * 4) + c16 * 16);
            const float* asrc = abase + (size_t)row * CC + kb * 32 + c16 * 4;
            const float* bsrc = wbase + (size_t)row * CC + kb * 32 + c16 * 4;
            cp16(da + doff, asrc);
            cp16(db + doff, bsrc);
        }
    };

    float acc[8][2][4];
#pragma unroll
    for (int nt = 0; nt < 8; ++nt)
#pragma unroll
        for (int mt = 0; mt < 2; ++mt)
#pragma unroll
            for (int i = 0; i < 4; ++i) acc[nt][mt][i] = 0.f;

    stage(0, 0);
    cp_commit();

    for (int kb = 0; kb < 8; ++kb) {
        int buf = kb & 1;
        __syncthreads();
        if (kb + 1 < 8) stage(buf ^ 1, kb + 1);
        cp_commit();
        cp_wait1();
        __syncthreads();

        const float* Ab = sm + buf * (128 * CSTR);
        const float* Bb = sm + 2 * (128 * CSTR) + buf * (128 * CSTR);

#pragma unroll
        for (int ks = 0; ks < 4; ++ks) {
            int k0 = ks * 8;
            uint32_t afr[2][4], bfr[8][2];
#pragma unroll
            for (int mt = 0; mt < 2; ++mt) {
                const float* p = Ab + (pm + mt * 16 + rr) * CSTR + k0 + q;
                afr[mt][0] = __float_as_uint(p[0]);
                afr[mt][1] = __float_as_uint(p[8 * CSTR]);
                afr[mt][2] = __float_as_uint(p[4]);
                afr[mt][3] = __float_as_uint(p[8 * CSTR + 4]);
            }
#pragma unroll
            for (int nt = 0; nt < 8; ++nt) {
                const float* p = Bb + (cn + nt * 8 + rr) * CSTR + k0 + q;
                bfr[nt][0] = __float_as_uint(p[0]);
                bfr[nt][1] = __float_as_uint(p[4]);
            }
#pragma unroll
            for (int nt = 0; nt < 8; ++nt)
#pragma unroll
                for (int mt = 0; mt < 2; ++mt)
                    mma8(acc[nt][mt], afr[mt], bfr[nt]);
        }
    }

    // epilogue: out = ska + D + bb2  (planar [co][pix])
    int q2 = q * 2;
#pragma unroll
    for (int nt = 0; nt < 8; ++nt) {
        int co = co0 + cn + nt * 8 + q2;
        float bbA = g_bb2[co], bbB = g_bb2[co + 1];
#pragma unroll
        for (int mt = 0; mt < 2; ++mt) {
            int pix = p0 + pm + mt * 16 + rr;
            size_t a0 = (size_t)(b * CC + co) * NPIX + pix;
            size_t a1 = a0 + NPIX;          // co+1
            out[a0]     = g_ska[a0]     + acc[nt][mt][0] + bbA;
            out[a1]     = g_ska[a1]     + acc[nt][mt][1] + bbB;
            out[a0 + 8] = g_ska[a0 + 8] + acc[nt][mt][2] + bbA;
            out[a1 + 8] = g_ska[a1 + 8] + acc[nt][mt][3] + bbB;
        }
    }
}

extern "C" void kernel_launch(void* const* d_in, const int* in_sizes, int n_in,
                              void* d_out, int out_size) {
    const float* x   = (const float*)d_in[0];
    const float* dw  = (const float*)d_in[1];
    const float* roi = (const float*)d_in[2];
    const float* w1  = (const float*)d_in[3];
    const float* g1  = (const float*)d_in[4];
    const float* b1  = (const float*)d_in[5];
    const float* m1  = (const float*)d_in[6];
    const float* v1  = (const float*)d_in[7];
    const float* w2  = (const float*)d_in[8];
    const float* g2  = (const float*)d_in[9];
    const float* b2  = (const float*)d_in[10];
    const float* m2  = (const float*)d_in[11];
    const float* v2  = (const float*)d_in[12];
    float* out = (float*)d_out;

    cudaFuncSetAttribute(conv3_mma,   cudaFuncAttributeMaxDynamicSharedMemorySize, C3_SMEM);
    cudaFuncSetAttribute(conv1x1_mma, cudaFuncAttributeMaxDynamicSharedMemorySize, SM1X1);

    prep_bn<<<1, 256>>>(g1, b1, m1, v1, g2, b2, m2, v2);
    prep_w2s<<<256, 256>>>(w2);
    ska_kernel<<<dim3(HH / 2, BB * GG), 256>>>(x, dw, roi);
    conv3_mma<<<dim3(8, 8, BB * GG), 256, C3_SMEM>>>(w1);
    conv1x1_mma<<<dim3(128, 2, BB), 256, SM1X1>>>(out);
}